// round 14
// baseline (speedup 1.0000x reference)
#include <cuda_runtime.h>
#include <cuda_fp16.h>
#include <math.h>
#include <stdint.h>

#define IN_DIM 164
#define KP0    192
#define HID    512
#define G4H    2048
#define BATCH  1024
#define MAXLEN 128
#define MAXT   (BATCH * (MAXLEN - 1))
#define RCTAS  128

// Gate permutation (fragment-aligned): permuted row n holds original row
// g*512 + U with  s=n>>6, a=(n>>4)&3, b2=(n>>3)&1, tg=(n>>1)&3, b=n&1,
// U = s*16 + a*4 + tg,  g = b2*2 + b.

// ===================== scratch (static device globals) ======================
__device__ __half g_fh[(long)MAXT * KP0];
__device__ __half g_x1[(long)MAXT * HID];
__device__ __half g_x2[(long)MAXT * HID];
__device__ __half g_xp[(long)MAXT * G4H];            // gate-permuted, fp16
__device__ __half g_we0[HID * KP0];
__device__ __half g_we1[HID * HID];
__device__ __half g_wl0[HID * HID];
__device__ __half g_wl1[HID * HID];
__device__ __half g_wihp[G4H * HID];                 // row-permuted
__device__ __half g_whhp[G4H * HID];                 // row-permuted
__device__ float  g_bsum[G4H];                       // bih+bhh, permuted
__device__ __half g_hbuf[2][BATCH * HID];
__device__ __half g_r0h[BATCH * HID];
__device__ __half g_r1h[BATCH * HID];
__device__ int    g_starts[BATCH];

// per-mi-group barriers, padded to 128B (own L2 line per group)
struct BarPad { unsigned v; unsigned pad[31]; };
__device__ BarPad g_barg[8];

// ===================== PTX helpers ==========================================
__device__ __forceinline__ uint32_t smem_u32(const void* p) {
    uint32_t a;
    asm("{ .reg .u64 t; cvta.to.shared.u64 t, %1; cvt.u32.u64 %0, t; }" : "=r"(a) : "l"(p));
    return a;
}
__device__ __forceinline__ void cp16(uint32_t dst, const void* src, int sz) {
    asm volatile("cp.async.cg.shared.global [%0], [%1], 16, %2;"
                 :: "r"(dst), "l"(src), "r"(sz));
}
__device__ __forceinline__ void cp_commit() {
    asm volatile("cp.async.commit_group;" ::: "memory");
}
#define CP_WAIT(n) asm volatile("cp.async.wait_group %0;" :: "n"(n) : "memory")

#define LDSM_X4(r, addr) \
    asm volatile("ldmatrix.sync.aligned.m8n8.x4.shared.b16 {%0,%1,%2,%3}, [%4];" \
        : "=r"((r)[0]), "=r"((r)[1]), "=r"((r)[2]), "=r"((r)[3]) : "r"(addr))

#define MMA16816(d, a, b0, b1) \
    asm volatile("mma.sync.aligned.m16n8k16.row.col.f32.f16.f16.f32 " \
        "{%0,%1,%2,%3}, {%4,%5,%6,%7}, {%8,%9}, {%0,%1,%2,%3};" \
        : "+f"((d)[0]), "+f"((d)[1]), "+f"((d)[2]), "+f"((d)[3]) \
        : "r"((a)[0]), "r"((a)[1]), "r"((a)[2]), "r"((a)[3]), "r"(b0), "r"(b1))

#define SWZ128(b) ((b) ^ (((b) >> 3) & 0x70))

// hardware tanh (MUFU.TANH) + sigmoid via tanh
__device__ __forceinline__ float tanha(float x) {
    float y;
    asm("tanh.approx.f32 %0, %1;" : "=f"(y) : "f"(x));
    return y;
}
__device__ __forceinline__ float siga(float x) {
    return fmaf(0.5f, tanha(0.5f * x), 0.5f);
}

// ===================== setup kernels ========================================
__global__ void scan_starts_kernel(const int* __restrict__ sizes, int* __restrict__ starts) {
    __shared__ int s[BATCH];
    int t = threadIdx.x;
    s[t] = sizes[t];
    __syncthreads();
    for (int off = 1; off < BATCH; off <<= 1) {
        int v = (t >= off) ? s[t - off] : 0;
        __syncthreads();
        s[t] += v;
        __syncthreads();
    }
    starts[t] = s[t] - sizes[t];
    if (t < 8) g_barg[t].v = 0u;
}

__device__ __forceinline__ int perm_orig_row(int n) {
    int s  = n >> 6;
    int a  = (n >> 4) & 3;
    int b2 = (n >> 3) & 1;
    int tg = (n >> 1) & 3;
    int b  = n & 1;
    int U  = s * 16 + a * 4 + tg;
    int gg = b2 * 2 + b;
    return gg * 512 + U;
}

__global__ void prep_bsum_kernel(const float* __restrict__ bih, const float* __restrict__ bhh,
                                 float* __restrict__ bsum) {
    int n = blockIdx.x * blockDim.x + threadIdx.x;
    if (n < G4H) {
        int orig = perm_orig_row(n);
        bsum[n] = bih[orig] + bhh[orig];
    }
}

// fused converts: feat(pad), We0(pad), We1, Wl0, Wl1 in one launch
__global__ void cvt_fused_kernel(const float* __restrict__ feat, __half* __restrict__ fh, long s_feat,
                                 const float* __restrict__ We0,  __half* __restrict__ we0,
                                 const float* __restrict__ We1,  __half* __restrict__ we1,
                                 const float* __restrict__ Wl0,  __half* __restrict__ wl0,
                                 const float* __restrict__ Wl1,  __half* __restrict__ wl1) {
    const long s_we0 = (long)HID * KP0;          // 98304
    const long s_sq  = (long)HID * HID;          // 262144
    long i = (long)blockIdx.x * blockDim.x + threadIdx.x;
    if (i < s_feat) {
        int r = (int)(i / KP0), c = (int)(i % KP0);
        float v = (c < IN_DIM) ? feat[(long)r * IN_DIM + c] : 0.f;
        fh[i] = __float2half(v);
        return;
    }
    i -= s_feat;
    if (i < s_we0) {
        int r = (int)(i / KP0), c = (int)(i % KP0);
        float v = (c < IN_DIM) ? We0[(long)r * IN_DIM + c] : 0.f;
        we0[i] = __float2half(v);
        return;
    }
    i -= s_we0;
    if (i < s_sq) { we1[i] = __float2half(We1[i]); return; }
    i -= s_sq;
    if (i < s_sq) { wl0[i] = __float2half(Wl0[i]); return; }
    i -= s_sq;
    if (i < s_sq) { wl1[i] = __float2half(Wl1[i]); }
}

// both 2048x512 weights, gate-permuted, in one launch
__global__ void cvt_wperm2_kernel(const float* __restrict__ Wih, const float* __restrict__ Whh,
                                  __half* __restrict__ oih, __half* __restrict__ ohh) {
    const long tot = (long)G4H * HID;
    long i = (long)blockIdx.x * blockDim.x + threadIdx.x;
    if (i >= 2 * tot) return;
    const float* W = (i < tot) ? Wih : Whh;
    __half* o      = (i < tot) ? oih : ohh;
    long j = (i < tot) ? i : i - tot;
    int n = (int)(j >> 9), k = (int)(j & 511);
    int orig = perm_orig_row(n);
    o[j] = __float2half(W[(long)orig * HID + k]);
}

// ===================== fp16 tensor GEMM =====================================
// EPI 1: bias+relu -> fp16.  EPI 2: plain -> fp16.
// EPI 3: relu(acc+bias) + resid(fp16) -> fp16 (tail residual MLP).
#define P_OFF_A  0
#define P_OFF_B  16384
#define P_STAGE  32768
#define P_SMEM   (2 * P_STAGE)

template<int EPI>
__global__ __launch_bounds__(256, 2)
void mm2(const __half* __restrict__ A, const __half* __restrict__ B,
         const float* __restrict__ bias, const __half* __restrict__ R,
         __half* __restrict__ C, int M, int N, int K)
{
    extern __shared__ char smem[];
    const uint32_t sb = smem_u32(smem);
    const int tid  = threadIdx.x;
    const int wid  = tid >> 5;
    const int lane = tid & 31;
    const int warp_m = wid & 3;
    const int warp_n = wid >> 2;

    const int m0 = blockIdx.y * 128;
    const int n0 = blockIdx.x * 128;
    const int nk = K >> 6;

    const int lrow = tid >> 1;
    const int qb = (tid & 1) * 4;
    const int arow = m0 + lrow;
    const int asz = (arow < M) ? 16 : 0;
    const long abase = (long)((arow < M) ? arow : (M - 1)) * K;
    const long bbase = (long)(n0 + lrow) * K;

    uint32_t sw_dst[4];
    #pragma unroll
    for (int i = 0; i < 4; i++)
        sw_dst[i] = (uint32_t)SWZ128(lrow * 128 + (qb + i) * 16);

    {
        #pragma unroll
        for (int i = 0; i < 4; i++) {
            const int q = qb + i;
            const uint32_t d = sb + sw_dst[i];
            cp16(d + P_OFF_A, A + abase + q * 8, asz);
            cp16(d + P_OFF_B, B + bbase + q * 8, 16);
        }
        cp_commit();
    }

    float acc[2][8][4];
    #pragma unroll
    for (int a = 0; a < 2; a++)
        #pragma unroll
        for (int b = 0; b < 8; b++)
            #pragma unroll
            for (int v = 0; v < 4; v++) acc[a][b][v] = 0.f;

    const int a_row = warp_m * 32 + (lane & 15);
    const int a_kq  = (lane >> 4) * 16;
    const int b_row = warp_n * 64 + (lane & 7) + ((lane >> 4) << 3);
    const int b_kq  = ((lane >> 3) & 1) * 16;

    for (int it = 0; it < nk; ++it) {
        const uint32_t cur = sb + (uint32_t)((it & 1) * P_STAGE);
        if (it + 1 < nk) {
            const uint32_t nxt = sb + (uint32_t)(((it + 1) & 1) * P_STAGE);
            const long ka = abase + (long)(it + 1) * 64;
            const long kb = bbase + (long)(it + 1) * 64;
            #pragma unroll
            for (int i = 0; i < 4; i++) {
                const int q = qb + i;
                const uint32_t d = nxt + sw_dst[i];
                cp16(d + P_OFF_A, A + ka + q * 8, asz);
                cp16(d + P_OFF_B, B + kb + q * 8, 16);
            }
            cp_commit();
            CP_WAIT(1);
        } else {
            CP_WAIT(0);
        }
        __syncthreads();

        #pragma unroll
        for (int ks = 0; ks < 4; ks++) {
            const int kbyte = ks * 32;
            uint32_t ah[2][4], bh[4][4];
            #pragma unroll
            for (int mf = 0; mf < 2; mf++) {
                const uint32_t ab = (uint32_t)SWZ128((a_row + mf * 16) * 128 + kbyte + a_kq);
                LDSM_X4(ah[mf], cur + P_OFF_A + ab);
            }
            #pragma unroll
            for (int p = 0; p < 4; p++) {
                const uint32_t bb = (uint32_t)SWZ128((b_row + p * 16) * 128 + kbyte + b_kq);
                LDSM_X4(bh[p], cur + P_OFF_B + bb);
            }
            #pragma unroll
            for (int mf = 0; mf < 2; mf++) {
                #pragma unroll
                for (int p = 0; p < 4; p++) {
                    MMA16816(acc[mf][2 * p],     ah[mf], bh[p][0], bh[p][1]);
                    MMA16816(acc[mf][2 * p + 1], ah[mf], bh[p][2], bh[p][3]);
                }
            }
        }
        __syncthreads();
    }

    const int g  = lane >> 2;
    const int tg = lane & 3;
    #pragma unroll
    for (int mf = 0; mf < 2; mf++) {
        const int r_base = m0 + warp_m * 32 + mf * 16 + g;
        #pragma unroll
        for (int ng = 0; ng < 8; ng++) {
            const int col = n0 + warp_n * 64 + ng * 8 + tg * 2;
            float b0 = 0.f, b1 = 0.f;
            if (EPI == 1 || EPI == 3) { b0 = bias[col]; b1 = bias[col + 1]; }
            #pragma unroll
            for (int half_i = 0; half_i < 2; half_i++) {
                const int r = r_base + half_i * 8;
                if (r >= M) continue;
                float v0 = acc[mf][ng][2 * half_i]     + b0;
                float v1 = acc[mf][ng][2 * half_i + 1] + b1;
                if (EPI == 1 || EPI == 3) { v0 = fmaxf(v0, 0.f); v1 = fmaxf(v1, 0.f); }
                if (EPI == 3) {
                    __half2 r2 = *(const __half2*)(R + (long)r * N + col);
                    float2 rf = __half22float2(r2);
                    v0 += rf.x;
                    v1 += rf.y;
                }
                __half2 h2 = __floats2half2_rn(v0, v1);
                *(uint32_t*)(C + (long)r * N + col) = *(uint32_t*)&h2;
            }
        }
    }
}

// ===================== persistent fused LSTM recurrence =====================
// 128 CTAs x 512 threads (16 warps, warp tile 32x32): mi=bid/16, ni=bid%16.
// Whh slice resident in smem; 3-stage A pipeline; xp for step t+1 prefetched
// BEFORE the step-t barrier; MUFU.TANH gates; padded per-mi-group barrier.
#define R_SM_B   0
#define R_SM_A   131072
#define R_STAGE  16384
#define R_SM_XP  (R_SM_A + 3 * R_STAGE)      // 180224
#define XP_PITCH 272
#define R_SM_H   (R_SM_XP + 128 * XP_PITCH)  // 215040
#define R_SMEM   (R_SM_H + 8192)             // 223232

__global__ __launch_bounds__(512, 1)
void lstm_persist(const __half* __restrict__ xp,
                  const int* __restrict__ sizes, const int* __restrict__ starts,
                  const float* __restrict__ bsum,
                  const __half* __restrict__ Whh,
                  __half* __restrict__ hbuf0, __half* __restrict__ hbuf1)
{
    extern __shared__ char smem[];
    const uint32_t sb = smem_u32(smem);
    const int tid  = threadIdx.x;
    const int wid  = tid >> 5;
    const int lane = tid & 31;
    const int warp_m = wid & 3;      // 4 warps along M (32 rows)
    const int warp_n = wid >> 2;     // 4 warps along N (32 cols)
    const int mi = blockIdx.x >> 4;
    const int ni = blockIdx.x & 15;
    const int m0 = mi * 128;
    const int n0 = ni * 128;

    // loaders: 512 threads, thread -> row tid/4, 2 chunks of 16B
    const int lrow = tid >> 2;
    const int qb = (tid & 3) * 2;
    const long abase = (long)(m0 + lrow) * HID;
    const long bbase = (long)(n0 + lrow) * HID;

    uint32_t sw_dst[2];
    #pragma unroll
    for (int i = 0; i < 2; i++)
        sw_dst[i] = (uint32_t)SWZ128(lrow * 128 + (qb + i) * 16);

    // ---- preload resident Whh slice ----
    #pragma unroll
    for (int it = 0; it < 8; it++) {
        #pragma unroll
        for (int i = 0; i < 2; i++) {
            const int q = qb + i;
            cp16(sb + R_SM_B + it * 16384 + sw_dst[i], Whh + bbase + it * 64 + q * 8, 16);
        }
    }
    cp_commit();

    const int a_row = warp_m * 32 + (lane & 15);
    const int a_kq  = (lane >> 4) * 16;
    const int b_row = warp_n * 32 + (lane & 7) + ((lane >> 4) << 3);
    const int b_kq  = ((lane >> 3) & 1) * 16;

    const int g  = lane >> 2;
    const int tg = lane & 3;
    const int col_base = n0 + warp_n * 32 + tg * 2;

    // xp prefetch mapping: thread row tid/4, 4 chunks of 16B at (tid&3)*64
    const int st_row = starts[m0 + (tid >> 2)];
    const int sz_row = sizes[m0 + (tid >> 2)];
    const uint32_t xdst = sb + R_SM_XP + (uint32_t)((tid >> 2) * XP_PITCH + (tid & 3) * 64);

    float bs0[4], bs1[4];
    #pragma unroll
    for (int ng = 0; ng < 4; ng++) {
        bs0[ng] = bsum[col_base + ng * 8];
        bs1[ng] = bsum[col_base + ng * 8 + 1];
    }

    float c_reg[2][2][2];   // [mf][a][hf]
    #pragma unroll
    for (int mf = 0; mf < 2; mf++)
        #pragma unroll
        for (int a = 0; a < 2; a++)
            #pragma unroll
            for (int hf = 0; hf < 2; hf++) c_reg[mf][a][hf] = 0.f;

    __half* bufs[2] = { hbuf0, hbuf1 };
    __half* hstage = (__half*)(smem + R_SM_H);
    const int jbase = (warp_n >> 1) * 16 + (warp_n & 1) * 8 + tg;

    // ---- xp prefetch for step 0 ----
    {
        const int xsz = (0 < sz_row) ? 16 : 0;
        const __half* xg = xp + ((long)(st_row + 0) * G4H + n0 + (tid & 3) * 32);
        #pragma unroll
        for (int q = 0; q < 4; q++)
            cp16(xdst + q * 16, xg + q * 8, xsz);
        cp_commit();
    }

    for (int t = 0; t < MAXLEN; t++) {
        float acc[2][4][4];
        #pragma unroll
        for (int a = 0; a < 2; a++)
            #pragma unroll
            for (int b = 0; b < 4; b++)
                #pragma unroll
                for (int v = 0; v < 4; v++) acc[a][b][v] = 0.f;

        if (t > 0) {
            const __half* hr = bufs[(t + 1) & 1];
            #pragma unroll
            for (int c = 0; c < 2; c++) {
                const long ka = abase + (long)c * 64;
                #pragma unroll
                for (int i = 0; i < 2; i++) {
                    const int q = qb + i;
                    cp16(sb + R_SM_A + (uint32_t)(c * R_STAGE) + sw_dst[i], hr + ka + q * 8, 16);
                }
                cp_commit();
            }

            int s_cur = 0, s_pf = 2;
            for (int it = 0; it < 8; ++it) {
                if (it < 7) { CP_WAIT(1); } else { CP_WAIT(0); }
                __syncthreads();
                if (it + 2 < 8) {
                    const long ka = abase + (long)(it + 2) * 64;
                    const uint32_t dstb = sb + R_SM_A + (uint32_t)(s_pf * R_STAGE);
                    #pragma unroll
                    for (int i = 0; i < 2; i++) {
                        const int q = qb + i;
                        cp16(dstb + sw_dst[i], hr + ka + q * 8, 16);
                    }
                    cp_commit();
                    s_pf = (s_pf == 2) ? 0 : s_pf + 1;
                }

                const uint32_t curA = sb + R_SM_A + (uint32_t)(s_cur * R_STAGE);
                const uint32_t curB = sb + R_SM_B + (uint32_t)(it * 16384);
                #pragma unroll
                for (int ks = 0; ks < 4; ks++) {
                    const int kbyte = ks * 32;
                    uint32_t ah[2][4], bh[2][4];
                    #pragma unroll
                    for (int mf = 0; mf < 2; mf++) {
                        const uint32_t ab = (uint32_t)SWZ128((a_row + mf * 16) * 128 + kbyte + a_kq);
                        LDSM_X4(ah[mf], curA + ab);
                    }
                    #pragma unroll
                    for (int p = 0; p < 2; p++) {
                        const uint32_t bb = (uint32_t)SWZ128((b_row + p * 16) * 128 + kbyte + b_kq);
                        LDSM_X4(bh[p], curB + bb);
                    }
                    #pragma unroll
                    for (int mf = 0; mf < 2; mf++) {
                        #pragma unroll
                        for (int p = 0; p < 2; p++) {
                            MMA16816(acc[mf][2 * p],     ah[mf], bh[p][0], bh[p][1]);
                            MMA16816(acc[mf][2 * p + 1], ah[mf], bh[p][2], bh[p][3]);
                        }
                    }
                }
                s_cur = (s_cur == 2) ? 0 : s_cur + 1;
            }
        } else {
            CP_WAIT(0);     // drain Whh preload + xp(0)
            __syncthreads();
        }

        // ---- fused gate epilogue (all gates in-thread) ----
        #pragma unroll
        for (int mf = 0; mf < 2; mf++) {
            #pragma unroll
            for (int hf = 0; hf < 2; hf++) {
                const int rloc = warp_m * 32 + mf * 16 + g + 8 * hf;
                const char* xrow_s = smem + R_SM_XP + rloc * XP_PITCH
                                   + (warp_n * 32 + tg * 2) * 2;
                #pragma unroll
                for (int a = 0; a < 2; a++) {
                    __half2 xif = *(const __half2*)(xrow_s + (2 * a) * 16);
                    __half2 xgo = *(const __half2*)(xrow_s + (2 * a + 1) * 16);
                    float2 fif = __half22float2(xif);
                    float2 fgo = __half22float2(xgo);
                    float gi = acc[mf][2 * a][2 * hf]         + bs0[2 * a]     + fif.x;
                    float gf = acc[mf][2 * a][2 * hf + 1]     + bs1[2 * a]     + fif.y;
                    float gg = acc[mf][2 * a + 1][2 * hf]     + bs0[2 * a + 1] + fgo.x;
                    float go = acc[mf][2 * a + 1][2 * hf + 1] + bs1[2 * a + 1] + fgo.y;
                    float cc = siga(gf) * c_reg[mf][a][hf] + siga(gi) * tanha(gg);
                    c_reg[mf][a][hf] = cc;
                    float hv = siga(go) * tanha(cc);
                    hstage[rloc * 32 + jbase + a * 4] = __float2half(hv);
                }
            }
        }
        __syncthreads();   // hstage ready; xp(t) fully consumed

        // ---- xp prefetch for NEXT step (overlaps with store + barrier) ----
        if (t < MAXLEN - 1) {
            const int tn = t + 1;
            const int xsz = (tn < sz_row) ? 16 : 0;
            const __half* xg = xp + ((long)(st_row + tn) * G4H + n0 + (tid & 3) * 32);
            #pragma unroll
            for (int q = 0; q < 4; q++)
                cp16(xdst + q * 16, xg + q * 8, xsz);
            cp_commit();
        }

        // ---- coalesced h store from stage (512 threads, 16B each) ----
        {
            __half* hw = bufs[t & 1];
            const int row = tid >> 2;
            const int off = (tid & 3) * 8;
            const __half* sp = hstage + row * 32 + off;
            uint4 v0 = *(const uint4*)(sp);
            __half* dst = hw + (long)(m0 + row) * HID + ni * 32 + off;
            *(uint4*)dst = v0;
        }

        // ---- per-group barrier (padded line; release/acquire, tight poll) ----
        if (t < MAXLEN - 1) {
            __syncthreads();
            if (tid == 0) {
                unsigned* bar = &g_barg[mi].v;
                asm volatile("red.release.gpu.add.u32 [%0], %1;" :: "l"(bar), "r"(1u) : "memory");
                const unsigned target = 16u * (unsigned)(t + 1);
                unsigned v;
                do {
                    asm volatile("ld.acquire.gpu.u32 %0, [%1];" : "=r"(v) : "l"(bar) : "memory");
                } while (v < target);
            }
            __syncthreads();
        }
    }
}

// ===================== decoder (fp16 input) =================================
__global__ __launch_bounds__(128)
void decoder_kernel(const __half* __restrict__ X, const float* __restrict__ Wd,
                    const float* __restrict__ bd, float* __restrict__ out)
{
    const int b = blockIdx.x;
    const int t = threadIdx.x;
    float s = 0.f;
    #pragma unroll
    for (int j = t; j < HID; j += 128) s += __half2float(X[(long)b * HID + j]) * Wd[j];
    s += __shfl_down_sync(0xffffffffu, s, 16);
    s += __shfl_down_sync(0xffffffffu, s, 8);
    s += __shfl_down_sync(0xffffffffu, s, 4);
    s += __shfl_down_sync(0xffffffffu, s, 2);
    s += __shfl_down_sync(0xffffffffu, s, 1);
    __shared__ float sh[4];
    if ((t & 31) == 0) sh[t >> 5] = s;
    __syncthreads();
    if (t == 0) out[b] = sh[0] + sh[1] + sh[2] + sh[3] + bd[0];
}

// ===================== host launcher ========================================
extern "C" void kernel_launch(void* const* d_in, const int* in_sizes, int n_in,
                              void* d_out, int out_size)
{
    const int*   sizes = (const int*)  d_in[0];
    const float* feat  = (const float*)d_in[1];
    const float* We0   = (const float*)d_in[2];
    const float* be0   = (const float*)d_in[3];
    const float* We1   = (const float*)d_in[4];
    const float* be1   = (const float*)d_in[5];
    const float* Wih   = (const float*)d_in[6];
    const float* bih   = (const float*)d_in[7];
    const float* Whh   = (const float*)d_in[8];
    const float* bhh   = (const float*)d_in[9];
    const float* Wl0   = (const float*)d_in[10];
    const float* bl0   = (const float*)d_in[11];
    const float* Wl1   = (const float*)d_in[12];
    const float* bl1   = (const float*)d_in[13];
    const float* Wd    = (const float*)d_in[14];
    const float* bd    = (const float*)d_in[15];
    float* out = (float*)d_out;

    const int T = in_sizes[1] / IN_DIM;
    const int mt = (T + 127) / 128;

    __half *fh, *x1, *x2, *xp, *we0, *we1, *wl0, *wl1, *wihp, *whhp, *hb0, *hb1, *r0h, *r1h;
    float *bsum;
    int* starts;
    cudaGetSymbolAddress((void**)&fh, g_fh);
    cudaGetSymbolAddress((void**)&x1, g_x1);
    cudaGetSymbolAddress((void**)&x2, g_x2);
    cudaGetSymbolAddress((void**)&xp, g_xp);
    cudaGetSymbolAddress((void**)&we0, g_we0);
    cudaGetSymbolAddress((void**)&we1, g_we1);
    cudaGetSymbolAddress((void**)&wl0, g_wl0);
    cudaGetSymbolAddress((void**)&wl1, g_wl1);
    cudaGetSymbolAddress((void**)&wihp, g_wihp);
    cudaGetSymbolAddress((void**)&whhp, g_whhp);
    cudaGetSymbolAddress((void**)&bsum, g_bsum);
    {
        __half* hb;
        cudaGetSymbolAddress((void**)&hb, g_hbuf);
        hb0 = hb;
        hb1 = hb + (long)BATCH * HID;
    }
    cudaGetSymbolAddress((void**)&r0h, g_r0h);
    cudaGetSymbolAddress((void**)&r1h, g_r1h);
    cudaGetSymbolAddress((void**)&starts, g_starts);

    cudaFuncSetAttribute(mm2<1>, cudaFuncAttributeMaxDynamicSharedMemorySize, P_SMEM);
    cudaFuncSetAttribute(mm2<2>, cudaFuncAttributeMaxDynamicSharedMemorySize, P_SMEM);
    cudaFuncSetAttribute(mm2<3>, cudaFuncAttributeMaxDynamicSharedMemorySize, P_SMEM);
    cudaFuncSetAttribute(lstm_persist, cudaFuncAttributeMaxDynamicSharedMemorySize, R_SMEM);

    scan_starts_kernel<<<1, BATCH>>>(sizes, starts);
    prep_bsum_kernel<<<(G4H + 255) / 256, 256>>>(bih, bhh, bsum);

    // fused converts (feat + 4 small weights), then gate-permuted big weights
    {
        const long s_feat = (long)T * KP0;
        const long total = s_feat + (long)HID * KP0 + 3L * HID * HID;
        cvt_fused_kernel<<<(int)((total + 255) / 256), 256>>>(
            feat, fh, s_feat, We0, we0, We1, we1, Wl0, wl0, Wl1, wl1);
        const long n = 2L * G4H * HID;
        cvt_wperm2_kernel<<<(int)((n + 255) / 256), 256>>>(Wih, Whh, wihp, whhp);
    }

    // encoder MLP + input projection (gate-permuted)
    mm2<1><<<dim3(HID / 128, mt), 256, P_SMEM>>>(fh, we0, be0, nullptr, x1, T, HID, KP0);
    mm2<1><<<dim3(HID / 128, mt), 256, P_SMEM>>>(x1, we1, be1, nullptr, x2, T, HID, HID);
    mm2<2><<<dim3(G4H / 128, mt), 256, P_SMEM>>>(x2, wihp, nullptr, nullptr, xp, T, G4H, HID);

    // persistent fused recurrence (512 threads, 16 warps)
    lstm_persist<<<RCTAS, 512, R_SMEM>>>(xp, sizes, starts, bsum, whhp, hb0, hb1);

    // tail: residual MLPs on tensor cores (h final is in hb1 = bufs[127&1])
    mm2<3><<<dim3(HID / 128, BATCH / 128), 256, P_SMEM>>>(hb1, wl0, bl0, hb1, r0h, BATCH, HID, HID);
    mm2<3><<<dim3(HID / 128, BATCH / 128), 256, P_SMEM>>>(r0h, wl1, bl1, r0h, r1h, BATCH, HID, HID);
    decoder_kernel<<<BATCH, 128>>>(r1h, Wd, bd, out);

    (void)n_in; (void)out_size;
}

// round 15
// speedup vs baseline: 1.7010x; 1.7010x over previous
#include <cuda_runtime.h>
#include <cuda_fp16.h>
#include <math.h>
#include <stdint.h>

#define IN_DIM 164
#define KP0    192
#define HID    512
#define G4H    2048
#define BATCH  1024
#define MAXLEN 128
#define MAXT   (BATCH * (MAXLEN - 1))
#define RCTAS  128

// Gate permutation (fragment-aligned): permuted row n holds original row
// g*512 + U with  s=n>>6, a=(n>>4)&3, b2=(n>>3)&1, tg=(n>>1)&3, b=n&1,
// U = s*16 + a*4 + tg,  g = b2*2 + b.

// ===================== scratch (static device globals) ======================
__device__ __half g_fh[(long)MAXT * KP0];
__device__ __half g_x1[(long)MAXT * HID];
__device__ __half g_x2[(long)MAXT * HID];
__device__ __half g_xp[(long)MAXT * G4H];            // gate-permuted, fp16
__device__ __half g_we0[HID * KP0];
__device__ __half g_we1[HID * HID];
__device__ __half g_wihp[G4H * HID];                 // row-permuted
__device__ __half g_whhp[G4H * HID];                 // row-permuted
__device__ float  g_bsum[G4H];                       // bih+bhh, permuted
__device__ __half g_hbuf[2][BATCH * HID];
__device__ float  g_hf32[BATCH * HID];
__device__ float  g_r0[BATCH * HID];
__device__ float  g_r1[BATCH * HID];
__device__ int    g_starts[BATCH];

// per-mi-group barriers, padded to 128B (own L2 line per group)
struct BarPad { unsigned v; unsigned pad[31]; };
__device__ BarPad g_barg[8];

// ===================== PTX helpers ==========================================
__device__ __forceinline__ uint32_t smem_u32(const void* p) {
    uint32_t a;
    asm("{ .reg .u64 t; cvta.to.shared.u64 t, %1; cvt.u32.u64 %0, t; }" : "=r"(a) : "l"(p));
    return a;
}
__device__ __forceinline__ void cp16(uint32_t dst, const void* src, int sz) {
    asm volatile("cp.async.cg.shared.global [%0], [%1], 16, %2;"
                 :: "r"(dst), "l"(src), "r"(sz));
}
__device__ __forceinline__ void cp_commit() {
    asm volatile("cp.async.commit_group;" ::: "memory");
}
#define CP_WAIT(n) asm volatile("cp.async.wait_group %0;" :: "n"(n) : "memory")

#define LDSM_X4(r, addr) \
    asm volatile("ldmatrix.sync.aligned.m8n8.x4.shared.b16 {%0,%1,%2,%3}, [%4];" \
        : "=r"((r)[0]), "=r"((r)[1]), "=r"((r)[2]), "=r"((r)[3]) : "r"(addr))

#define MMA16816(d, a, b0, b1) \
    asm volatile("mma.sync.aligned.m16n8k16.row.col.f32.f16.f16.f32 " \
        "{%0,%1,%2,%3}, {%4,%5,%6,%7}, {%8,%9}, {%0,%1,%2,%3};" \
        : "+f"((d)[0]), "+f"((d)[1]), "+f"((d)[2]), "+f"((d)[3]) \
        : "r"((a)[0]), "r"((a)[1]), "r"((a)[2]), "r"((a)[3]), "r"(b0), "r"(b1))

#define SWZ128(b) ((b) ^ (((b) >> 3) & 0x70))

// hardware tanh (MUFU.TANH) + sigmoid via tanh
__device__ __forceinline__ float tanha(float x) {
    float y;
    asm("tanh.approx.f32 %0, %1;" : "=f"(y) : "f"(x));
    return y;
}
__device__ __forceinline__ float siga(float x) {
    return fmaf(0.5f, tanha(0.5f * x), 0.5f);
}

// ===================== setup kernels ========================================
__global__ void scan_starts_kernel(const int* __restrict__ sizes, int* __restrict__ starts) {
    __shared__ int s[BATCH];
    int t = threadIdx.x;
    s[t] = sizes[t];
    __syncthreads();
    for (int off = 1; off < BATCH; off <<= 1) {
        int v = (t >= off) ? s[t - off] : 0;
        __syncthreads();
        s[t] += v;
        __syncthreads();
    }
    starts[t] = s[t] - sizes[t];
    if (t < 8) g_barg[t].v = 0u;
}

__device__ __forceinline__ int perm_orig_row(int n) {
    int s  = n >> 6;
    int a  = (n >> 4) & 3;
    int b2 = (n >> 3) & 1;
    int tg = (n >> 1) & 3;
    int b  = n & 1;
    int U  = s * 16 + a * 4 + tg;
    int gg = b2 * 2 + b;
    return gg * 512 + U;
}

__global__ void prep_bsum_kernel(const float* __restrict__ bih, const float* __restrict__ bhh,
                                 float* __restrict__ bsum) {
    int n = blockIdx.x * blockDim.x + threadIdx.x;
    if (n < G4H) {
        int orig = perm_orig_row(n);
        bsum[n] = bih[orig] + bhh[orig];
    }
}

__global__ void cvt_kernel(const float* __restrict__ X, __half* __restrict__ out,
                           int M, int K, int Kp) {
    long i = (long)blockIdx.x * blockDim.x + threadIdx.x;
    if (i >= (long)M * Kp) return;
    int r = (int)(i / Kp), cidx = (int)(i % Kp);
    float v = (cidx < K) ? X[(long)r * K + cidx] : 0.f;
    out[i] = __float2half(v);
}

// both 2048x512 weights, gate-permuted, in one launch
__global__ void cvt_wperm2_kernel(const float* __restrict__ Wih, const float* __restrict__ Whh,
                                  __half* __restrict__ oih, __half* __restrict__ ohh) {
    const long tot = (long)G4H * HID;
    long i = (long)blockIdx.x * blockDim.x + threadIdx.x;
    if (i >= 2 * tot) return;
    const float* W = (i < tot) ? Wih : Whh;
    __half* o      = (i < tot) ? oih : ohh;
    long j = (i < tot) ? i : i - tot;
    int n = (int)(j >> 9), k = (int)(j & 511);
    int orig = perm_orig_row(n);
    o[j] = __float2half(W[(long)orig * HID + k]);
}

// ===================== fp16 tensor GEMM (parallel section) ==================
#define P_OFF_A  0
#define P_OFF_B  16384
#define P_STAGE  32768
#define P_SMEM   (2 * P_STAGE)

template<int EPI>
__global__ __launch_bounds__(256, 2)
void mm2(const __half* __restrict__ A, const __half* __restrict__ B,
         const float* __restrict__ bias, __half* __restrict__ C,
         int M, int N, int K)
{
    extern __shared__ char smem[];
    const uint32_t sb = smem_u32(smem);
    const int tid  = threadIdx.x;
    const int wid  = tid >> 5;
    const int lane = tid & 31;
    const int warp_m = wid & 3;
    const int warp_n = wid >> 2;

    const int m0 = blockIdx.y * 128;
    const int n0 = blockIdx.x * 128;
    const int nk = K >> 6;

    const int lrow = tid >> 1;
    const int qb = (tid & 1) * 4;
    const int arow = m0 + lrow;
    const int asz = (arow < M) ? 16 : 0;
    const long abase = (long)((arow < M) ? arow : (M - 1)) * K;
    const long bbase = (long)(n0 + lrow) * K;

    uint32_t sw_dst[4];
    #pragma unroll
    for (int i = 0; i < 4; i++)
        sw_dst[i] = (uint32_t)SWZ128(lrow * 128 + (qb + i) * 16);

    {
        #pragma unroll
        for (int i = 0; i < 4; i++) {
            const int q = qb + i;
            const uint32_t d = sb + sw_dst[i];
            cp16(d + P_OFF_A, A + abase + q * 8, asz);
            cp16(d + P_OFF_B, B + bbase + q * 8, 16);
        }
        cp_commit();
    }

    float acc[2][8][4];
    #pragma unroll
    for (int a = 0; a < 2; a++)
        #pragma unroll
        for (int b = 0; b < 8; b++)
            #pragma unroll
            for (int v = 0; v < 4; v++) acc[a][b][v] = 0.f;

    const int a_row = warp_m * 32 + (lane & 15);
    const int a_kq  = (lane >> 4) * 16;
    const int b_row = warp_n * 64 + (lane & 7) + ((lane >> 4) << 3);
    const int b_kq  = ((lane >> 3) & 1) * 16;

    for (int it = 0; it < nk; ++it) {
        const uint32_t cur = sb + (uint32_t)((it & 1) * P_STAGE);
        if (it + 1 < nk) {
            const uint32_t nxt = sb + (uint32_t)(((it + 1) & 1) * P_STAGE);
            const long ka = abase + (long)(it + 1) * 64;
            const long kb = bbase + (long)(it + 1) * 64;
            #pragma unroll
            for (int i = 0; i < 4; i++) {
                const int q = qb + i;
                const uint32_t d = nxt + sw_dst[i];
                cp16(d + P_OFF_A, A + ka + q * 8, asz);
                cp16(d + P_OFF_B, B + kb + q * 8, 16);
            }
            cp_commit();
            CP_WAIT(1);
        } else {
            CP_WAIT(0);
        }
        __syncthreads();

        #pragma unroll
        for (int ks = 0; ks < 4; ks++) {
            const int kbyte = ks * 32;
            uint32_t ah[2][4], bh[4][4];
            #pragma unroll
            for (int mf = 0; mf < 2; mf++) {
                const uint32_t ab = (uint32_t)SWZ128((a_row + mf * 16) * 128 + kbyte + a_kq);
                LDSM_X4(ah[mf], cur + P_OFF_A + ab);
            }
            #pragma unroll
            for (int p = 0; p < 4; p++) {
                const uint32_t bb = (uint32_t)SWZ128((b_row + p * 16) * 128 + kbyte + b_kq);
                LDSM_X4(bh[p], cur + P_OFF_B + bb);
            }
            #pragma unroll
            for (int mf = 0; mf < 2; mf++) {
                #pragma unroll
                for (int p = 0; p < 4; p++) {
                    MMA16816(acc[mf][2 * p],     ah[mf], bh[p][0], bh[p][1]);
                    MMA16816(acc[mf][2 * p + 1], ah[mf], bh[p][2], bh[p][3]);
                }
            }
        }
        __syncthreads();
    }

    const int g  = lane >> 2;
    const int tg = lane & 3;
    #pragma unroll
    for (int mf = 0; mf < 2; mf++) {
        const int r_base = m0 + warp_m * 32 + mf * 16 + g;
        #pragma unroll
        for (int ng = 0; ng < 8; ng++) {
            const int col = n0 + warp_n * 64 + ng * 8 + tg * 2;
            float b0 = 0.f, b1 = 0.f;
            if (EPI == 1) { b0 = bias[col]; b1 = bias[col + 1]; }
            #pragma unroll
            for (int half_i = 0; half_i < 2; half_i++) {
                const int r = r_base + half_i * 8;
                if (r >= M) continue;
                float v0 = acc[mf][ng][2 * half_i]     + b0;
                float v1 = acc[mf][ng][2 * half_i + 1] + b1;
                if (EPI == 1) { v0 = fmaxf(v0, 0.f); v1 = fmaxf(v1, 0.f); }
                __half2 h2 = __floats2half2_rn(v0, v1);
                *(uint32_t*)(C + (long)r * N + col) = *(uint32_t*)&h2;
            }
        }
    }
}

// ===================== persistent fused LSTM recurrence =====================
// 128 CTAs x 512 threads (16 warps, warp tile 32x32): mi=bid/16, ni=bid%16.
// Whh slice resident in smem; 3-stage A pipeline; xp for step t+1 prefetched
// BEFORE the step-t barrier (overlaps DRAM latency with barrier wait);
// MUFU.TANH gates; padded per-mi-group barrier.
#define R_SM_B   0
#define R_SM_A   131072
#define R_STAGE  16384
#define R_SM_XP  (R_SM_A + 3 * R_STAGE)      // 180224
#define XP_PITCH 272
#define R_SM_H   (R_SM_XP + 128 * XP_PITCH)  // 215040
#define R_SMEM   (R_SM_H + 8192)             // 223232

__global__ __launch_bounds__(512, 1)
void lstm_persist(const __half* __restrict__ xp,
                  const int* __restrict__ sizes, const int* __restrict__ starts,
                  const float* __restrict__ bsum,
                  const __half* __restrict__ Whh,
                  __half* __restrict__ hbuf0, __half* __restrict__ hbuf1,
                  float* __restrict__ hf32)
{
    extern __shared__ char smem[];
    const uint32_t sb = smem_u32(smem);
    const int tid  = threadIdx.x;
    const int wid  = tid >> 5;
    const int lane = tid & 31;
    const int warp_m = wid & 3;      // 4 warps along M (32 rows)
    const int warp_n = wid >> 2;     // 4 warps along N (32 cols)
    const int mi = blockIdx.x >> 4;
    const int ni = blockIdx.x & 15;
    const int m0 = mi * 128;
    const int n0 = ni * 128;

    // loaders: 512 threads, thread -> row tid/4, 2 chunks of 16B
    const int lrow = tid >> 2;
    const int qb = (tid & 3) * 2;
    const long abase = (long)(m0 + lrow) * HID;
    const long bbase = (long)(n0 + lrow) * HID;

    uint32_t sw_dst[2];
    #pragma unroll
    for (int i = 0; i < 2; i++)
        sw_dst[i] = (uint32_t)SWZ128(lrow * 128 + (qb + i) * 16);

    // ---- preload resident Whh slice ----
    #pragma unroll
    for (int it = 0; it < 8; it++) {
        #pragma unroll
        for (int i = 0; i < 2; i++) {
            const int q = qb + i;
            cp16(sb + R_SM_B + it * 16384 + sw_dst[i], Whh + bbase + it * 64 + q * 8, 16);
        }
    }
    cp_commit();

    const int a_row = warp_m * 32 + (lane & 15);
    const int a_kq  = (lane >> 4) * 16;
    const int b_row = warp_n * 32 + (lane & 7) + ((lane >> 4) << 3);
    const int b_kq  = ((lane >> 3) & 1) * 16;

    const int g  = lane >> 2;
    const int tg = lane & 3;
    const int col_base = n0 + warp_n * 32 + tg * 2;

    // xp prefetch mapping: thread row tid/4, 4 chunks of 16B at (tid&3)*64
    const int st_row = starts[m0 + (tid >> 2)];
    const int sz_row = sizes[m0 + (tid >> 2)];
    const uint32_t xdst = sb + R_SM_XP + (uint32_t)((tid >> 2) * XP_PITCH + (tid & 3) * 64);

    float bs0[4], bs1[4];
    #pragma unroll
    for (int ng = 0; ng < 4; ng++) {
        bs0[ng] = bsum[col_base + ng * 8];
        bs1[ng] = bsum[col_base + ng * 8 + 1];
    }

    float c_reg[2][2][2];   // [mf][a][hf]
    #pragma unroll
    for (int mf = 0; mf < 2; mf++)
        #pragma unroll
        for (int a = 0; a < 2; a++)
            #pragma unroll
            for (int hf = 0; hf < 2; hf++) c_reg[mf][a][hf] = 0.f;

    __half* bufs[2] = { hbuf0, hbuf1 };
    __half* hstage = (__half*)(smem + R_SM_H);
    const int jbase = (warp_n >> 1) * 16 + (warp_n & 1) * 8 + tg;

    // ---- xp prefetch for step 0 ----
    {
        const int xsz = (0 < sz_row) ? 16 : 0;
        const __half* xg = xp + ((long)(st_row + 0) * G4H + n0 + (tid & 3) * 32);
        #pragma unroll
        for (int q = 0; q < 4; q++)
            cp16(xdst + q * 16, xg + q * 8, xsz);
        cp_commit();
    }

    for (int t = 0; t < MAXLEN; t++) {
        float acc[2][4][4];
        #pragma unroll
        for (int a = 0; a < 2; a++)
            #pragma unroll
            for (int b = 0; b < 4; b++)
                #pragma unroll
                for (int v = 0; v < 4; v++) acc[a][b][v] = 0.f;

        if (t > 0) {
            const __half* hr = bufs[(t + 1) & 1];
            #pragma unroll
            for (int c = 0; c < 2; c++) {
                const long ka = abase + (long)c * 64;
                #pragma unroll
                for (int i = 0; i < 2; i++) {
                    const int q = qb + i;
                    cp16(sb + R_SM_A + (uint32_t)(c * R_STAGE) + sw_dst[i], hr + ka + q * 8, 16);
                }
                cp_commit();
            }

            int s_cur = 0, s_pf = 2;
            for (int it = 0; it < 8; ++it) {
                if (it < 7) { CP_WAIT(1); } else { CP_WAIT(0); }
                __syncthreads();
                if (it + 2 < 8) {
                    const long ka = abase + (long)(it + 2) * 64;
                    const uint32_t dstb = sb + R_SM_A + (uint32_t)(s_pf * R_STAGE);
                    #pragma unroll
                    for (int i = 0; i < 2; i++) {
                        const int q = qb + i;
                        cp16(dstb + sw_dst[i], hr + ka + q * 8, 16);
                    }
                    cp_commit();
                    s_pf = (s_pf == 2) ? 0 : s_pf + 1;
                }

                const uint32_t curA = sb + R_SM_A + (uint32_t)(s_cur * R_STAGE);
                const uint32_t curB = sb + R_SM_B + (uint32_t)(it * 16384);
                #pragma unroll
                for (int ks = 0; ks < 4; ks++) {
                    const int kbyte = ks * 32;
                    uint32_t ah[2][4], bh[2][4];
                    #pragma unroll
                    for (int mf = 0; mf < 2; mf++) {
                        const uint32_t ab = (uint32_t)SWZ128((a_row + mf * 16) * 128 + kbyte + a_kq);
                        LDSM_X4(ah[mf], curA + ab);
                    }
                    #pragma unroll
                    for (int p = 0; p < 2; p++) {
                        const uint32_t bb = (uint32_t)SWZ128((b_row + p * 16) * 128 + kbyte + b_kq);
                        LDSM_X4(bh[p], curB + bb);
                    }
                    #pragma unroll
                    for (int mf = 0; mf < 2; mf++) {
                        #pragma unroll
                        for (int p = 0; p < 2; p++) {
                            MMA16816(acc[mf][2 * p],     ah[mf], bh[p][0], bh[p][1]);
                            MMA16816(acc[mf][2 * p + 1], ah[mf], bh[p][2], bh[p][3]);
                        }
                    }
                }
                s_cur = (s_cur == 2) ? 0 : s_cur + 1;
            }
        } else {
            CP_WAIT(0);     // drain Whh preload + xp(0)
            __syncthreads();
        }

        // ---- fused gate epilogue (all gates in-thread) ----
        #pragma unroll
        for (int mf = 0; mf < 2; mf++) {
            #pragma unroll
            for (int hf = 0; hf < 2; hf++) {
                const int rloc = warp_m * 32 + mf * 16 + g + 8 * hf;
                const char* xrow_s = smem + R_SM_XP + rloc * XP_PITCH
                                   + (warp_n * 32 + tg * 2) * 2;
                #pragma unroll
                for (int a = 0; a < 2; a++) {
                    __half2 xif = *(const __half2*)(xrow_s + (2 * a) * 16);
                    __half2 xgo = *(const __half2*)(xrow_s + (2 * a + 1) * 16);
                    float2 fif = __half22float2(xif);
                    float2 fgo = __half22float2(xgo);
                    float gi = acc[mf][2 * a][2 * hf]         + bs0[2 * a]     + fif.x;
                    float gf = acc[mf][2 * a][2 * hf + 1]     + bs1[2 * a]     + fif.y;
                    float gg = acc[mf][2 * a + 1][2 * hf]     + bs0[2 * a + 1] + fgo.x;
                    float go = acc[mf][2 * a + 1][2 * hf + 1] + bs1[2 * a + 1] + fgo.y;
                    float cc = siga(gf) * c_reg[mf][a][hf] + siga(gi) * tanha(gg);
                    c_reg[mf][a][hf] = cc;
                    float hv = siga(go) * tanha(cc);
                    hstage[rloc * 32 + jbase + a * 4] = __float2half(hv);
                }
            }
        }
        __syncthreads();   // hstage ready; xp(t) fully consumed

        // ---- xp prefetch for NEXT step (overlaps with store + barrier) ----
        if (t < MAXLEN - 1) {
            const int tn = t + 1;
            const int xsz = (tn < sz_row) ? 16 : 0;
            const __half* xg = xp + ((long)(st_row + tn) * G4H + n0 + (tid & 3) * 32);
            #pragma unroll
            for (int q = 0; q < 4; q++)
                cp16(xdst + q * 16, xg + q * 8, xsz);
            cp_commit();
        }

        // ---- coalesced h store from stage (512 threads, 16B each) ----
        {
            __half* hw = bufs[t & 1];
            const int row = tid >> 2;
            const int off = (tid & 3) * 8;
            const __half* sp = hstage + row * 32 + off;
            uint4 v0 = *(const uint4*)(sp);
            __half* dst = hw + (long)(m0 + row) * HID + ni * 32 + off;
            *(uint4*)dst = v0;
            if (t == MAXLEN - 1) {
                float* fd = hf32 + (long)(m0 + row) * HID + ni * 32 + off;
                #pragma unroll
                for (int k2 = 0; k2 < 8; k2++) fd[k2] = __half2float(sp[k2]);
            }
        }

        // ---- per-group barrier (padded line; release/acquire, tight poll) ----
        if (t < MAXLEN - 1) {
            __syncthreads();
            if (tid == 0) {
                unsigned* bar = &g_barg[mi].v;
                asm volatile("red.release.gpu.add.u32 [%0], %1;" :: "l"(bar), "r"(1u) : "memory");
                const unsigned target = 16u * (unsigned)(t + 1);
                unsigned v;
                do {
                    asm volatile("ld.acquire.gpu.u32 %0, [%1];" : "=r"(v) : "l"(bar) : "memory");
                } while (v < target);
            }
            __syncthreads();
        }
    }
}

// ===================== fp32 SGEMM (tail) ====================================
template<bool RELU, bool RESID, bool BIAS>
__global__ __launch_bounds__(256)
void sgemm_nt(const float* __restrict__ A, const float* __restrict__ W,
              const float* __restrict__ bias, const float* __restrict__ R,
              float* __restrict__ C, int M, int N, int K)
{
    constexpr int BM = 64, BN = 64, BK = 16;
    __shared__ float As[BK][BM];
    __shared__ float Bs[BK][BN];
    const int tid = threadIdx.x;
    const int brow = blockIdx.y * BM;
    const int bcol = blockIdx.x * BN;
    const int tr = (tid / 16) * 4;
    const int tc = (tid % 16) * 4;
    const int lr = tid / 4;
    const int lc = (tid % 4) * 4;
    float acc[4][4] = {};
    for (int k0 = 0; k0 < K; k0 += BK) {
        {
            int ar = brow + lr;
            float4 v = *reinterpret_cast<const float4*>(&A[(long)ar * K + k0 + lc]);
            As[lc + 0][lr] = v.x; As[lc + 1][lr] = v.y; As[lc + 2][lr] = v.z; As[lc + 3][lr] = v.w;
        }
        {
            int wr = bcol + lr;
            float4 v = *reinterpret_cast<const float4*>(&W[(long)wr * K + k0 + lc]);
            Bs[lc + 0][lr] = v.x; Bs[lc + 1][lr] = v.y; Bs[lc + 2][lr] = v.z; Bs[lc + 3][lr] = v.w;
        }
        __syncthreads();
        #pragma unroll
        for (int kk = 0; kk < BK; kk++) {
            float a[4], b[4];
            #pragma unroll
            for (int i = 0; i < 4; i++) a[i] = As[kk][tr + i];
            #pragma unroll
            for (int j = 0; j < 4; j++) b[j] = Bs[kk][tc + j];
            #pragma unroll
            for (int i = 0; i < 4; i++)
                #pragma unroll
                for (int j = 0; j < 4; j++)
                    acc[i][j] = fmaf(a[i], b[j], acc[i][j]);
        }
        __syncthreads();
    }
    #pragma unroll
    for (int i = 0; i < 4; i++) {
        int r = brow + tr + i;
        #pragma unroll
        for (int j = 0; j < 4; j++) {
            int cidx = bcol + tc + j;
            float v = acc[i][j];
            if (BIAS)  v += bias[cidx];
            if (RELU)  v = fmaxf(v, 0.f);
            if (RESID) v += R[(long)r * N + cidx];
            C[(long)r * N + cidx] = v;
        }
    }
}

// ===================== decoder ==============================================
__global__ __launch_bounds__(128)
void decoder_kernel(const float* __restrict__ X, const float* __restrict__ Wd,
                    const float* __restrict__ bd, float* __restrict__ out)
{
    const int b = blockIdx.x;
    const int t = threadIdx.x;
    float s = 0.f;
    #pragma unroll
    for (int j = t; j < HID; j += 128) s += X[(long)b * HID + j] * Wd[j];
    s += __shfl_down_sync(0xffffffffu, s, 16);
    s += __shfl_down_sync(0xffffffffu, s, 8);
    s += __shfl_down_sync(0xffffffffu, s, 4);
    s += __shfl_down_sync(0xffffffffu, s, 2);
    s += __shfl_down_sync(0xffffffffu, s, 1);
    __shared__ float sh[4];
    if ((t & 31) == 0) sh[t >> 5] = s;
    __syncthreads();
    if (t == 0) out[b] = sh[0] + sh[1] + sh[2] + sh[3] + bd[0];
}

// ===================== host launcher ========================================
extern "C" void kernel_launch(void* const* d_in, const int* in_sizes, int n_in,
                              void* d_out, int out_size)
{
    const int*   sizes = (const int*)  d_in[0];
    const float* feat  = (const float*)d_in[1];
    const float* We0   = (const float*)d_in[2];
    const float* be0   = (const float*)d_in[3];
    const float* We1   = (const float*)d_in[4];
    const float* be1   = (const float*)d_in[5];
    const float* Wih   = (const float*)d_in[6];
    const float* bih   = (const float*)d_in[7];
    const float* Whh   = (const float*)d_in[8];
    const float* bhh   = (const float*)d_in[9];
    const float* Wl0   = (const float*)d_in[10];
    const float* bl0   = (const float*)d_in[11];
    const float* Wl1   = (const float*)d_in[12];
    const float* bl1   = (const float*)d_in[13];
    const float* Wd    = (const float*)d_in[14];
    const float* bd    = (const float*)d_in[15];
    float* out = (float*)d_out;

    const int T = in_sizes[1] / IN_DIM;
    const int mt = (T + 127) / 128;

    __half *fh, *x1, *x2, *xp, *we0, *we1, *wihp, *whhp, *hb0, *hb1;
    float *bsum, *hf32, *r0, *r1;
    int* starts;
    cudaGetSymbolAddress((void**)&fh, g_fh);
    cudaGetSymbolAddress((void**)&x1, g_x1);
    cudaGetSymbolAddress((void**)&x2, g_x2);
    cudaGetSymbolAddress((void**)&xp, g_xp);
    cudaGetSymbolAddress((void**)&we0, g_we0);
    cudaGetSymbolAddress((void**)&we1, g_we1);
    cudaGetSymbolAddress((void**)&wihp, g_wihp);
    cudaGetSymbolAddress((void**)&whhp, g_whhp);
    cudaGetSymbolAddress((void**)&bsum, g_bsum);
    {
        __half* hb;
        cudaGetSymbolAddress((void**)&hb, g_hbuf);
        hb0 = hb;
        hb1 = hb + (long)BATCH * HID;
    }
    cudaGetSymbolAddress((void**)&hf32, g_hf32);
    cudaGetSymbolAddress((void**)&r0, g_r0);
    cudaGetSymbolAddress((void**)&r1, g_r1);
    cudaGetSymbolAddress((void**)&starts, g_starts);

    cudaFuncSetAttribute(mm2<1>, cudaFuncAttributeMaxDynamicSharedMemorySize, P_SMEM);
    cudaFuncSetAttribute(mm2<2>, cudaFuncAttributeMaxDynamicSharedMemorySize, P_SMEM);
    cudaFuncSetAttribute(lstm_persist, cudaFuncAttributeMaxDynamicSharedMemorySize, R_SMEM);

    scan_starts_kernel<<<1, BATCH>>>(sizes, starts);
    prep_bsum_kernel<<<(G4H + 255) / 256, 256>>>(bih, bhh, bsum);

    // converts (fp16)
    {
        long n;
        n = (long)T * KP0;
        cvt_kernel<<<(int)((n + 255) / 256), 256>>>(feat, fh, T, IN_DIM, KP0);
        n = (long)HID * KP0;
        cvt_kernel<<<(int)((n + 255) / 256), 256>>>(We0, we0, HID, IN_DIM, KP0);
        n = (long)HID * HID;
        cvt_kernel<<<(int)((n + 255) / 256), 256>>>(We1, we1, HID, HID, HID);
        n = 2L * G4H * HID;
        cvt_wperm2_kernel<<<(int)((n + 255) / 256), 256>>>(Wih, Whh, wihp, whhp);
    }

    // encoder MLP + input projection (gate-permuted)
    mm2<1><<<dim3(HID / 128, mt), 256, P_SMEM>>>(fh, we0, be0, x1, T, HID, KP0);
    mm2<1><<<dim3(HID / 128, mt), 256, P_SMEM>>>(x1, we1, be1, x2, T, HID, HID);
    mm2<2><<<dim3(G4H / 128, mt), 256, P_SMEM>>>(x2, wihp, nullptr, xp, T, G4H, HID);

    // persistent fused recurrence (512 threads, 16 warps)
    lstm_persist<<<RCTAS, 512, R_SMEM>>>(xp, sizes, starts, bsum, whhp, hb0, hb1, hf32);

    // tail
    sgemm_nt<true, true, true><<<dim3(HID / 64, BATCH / 64), 256>>>(hf32, Wl0, bl0, hf32, r0, BATCH, HID, HID);
    sgemm_nt<true, true, true><<<dim3(HID / 64, BATCH / 64), 256>>>(r0,   Wl1, bl1, r0,   r1, BATCH, HID, HID);
    decoder_kernel<<<BATCH, 128>>>(r1, Wd, bd, out);

    (void)n_in; (void)out_size;
}